// round 13
// baseline (speedup 1.0000x reference)
#include <cuda_runtime.h>

// SrbQpCtrl: tau = zeros([2e6,10], f32) = 80 MB constant fill (input x unused;
// QP with Q=I, q=0, z>=0 has closed-form optimum z*=0; broadcast -> zeros).
//
// FINAL — stationary across R5/R7-R12 (kernel 12.38-12.83 us, wall
// 14.72-15.07 us; wall jitter is replay overhead, uncorrelated with kernel
// time). Established over twelve rounds: CE memset, SIMT STG.E.128 (three
// layouts), and TMA bulk S2G all converge at ~3100 B/cyc — the sm_103a
// chip-level L2 WRITE-port cap (half the 6300 B/cyc LTS read cap;
// byte-bound, path-independent, chip-shared). The 80 MB write is mandatory
// (d_out poisoned to 0xAA before every timed replay). Floor:
// 80 MB / 3100 B/cyc ≈ 12.6 us kernel + ~2.2 us graph-replay overhead
// ≈ 14.8 us wall. This kernel sits on that floor.
//
// Layout: exact cover, 512 float4 per block, two block-interleaved
// fully-coalesced STG.E.128 per thread — each store instruction's warp
// footprint is one contiguous 128B-aligned 512 B span, giving full-sector
// L2 writes and zero read-modify-write traffic (the only axis measurements
// showed to matter; breaking it cost +75% in R3).

__global__ void __launch_bounds__(256) zero_fill_exact(float4* __restrict__ out, int n4) {
    int base = blockIdx.x * 512 + threadIdx.x;   // block covers [blk*512, blk*512+512)
    const float4 z = make_float4(0.f, 0.f, 0.f, 0.f);
    if (base < n4)        out[base] = z;         // float4 0..255 of the block span
    if (base + 256 < n4)  out[base + 256] = z;   // float4 256..511
}

extern "C" void kernel_launch(void* const* d_in, const int* in_sizes, int n_in,
                              void* d_out, int out_size) {
    (void)d_in; (void)in_sizes; (void)n_in;
    int n4 = out_size / 4;                       // 5,000,000 float4
    int blocks = (n4 + 511) / 512;               // 9766 blocks, exact cover
    zero_fill_exact<<<blocks, 256>>>((float4*)d_out, n4);

    int tail = out_size - n4 * 4;                // 0 for 20M floats; defensive
    if (tail > 0)
        cudaMemsetAsync((float*)d_out + (size_t)n4 * 4, 0, (size_t)tail * sizeof(float), 0);
}

// round 14
// speedup vs baseline: 1.0194x; 1.0194x over previous
#include <cuda_runtime.h>

// SrbQpCtrl: tau = zeros([2e6,10], f32) = 80 MB constant fill (input x unused;
// QP with Q=I, q=0, z>=0 has closed-form optimum z*=0; broadcast -> zeros).
//
// FINAL — stationary across R5/R7-R13 (kernel 12.38-12.83 us, wall
// 14.72-15.10 us; wall jitter is replay overhead, uncorrelated with kernel
// time). Established over thirteen rounds: CE memset, SIMT STG.E.128 (three
// layouts), and TMA bulk S2G all converge at ~3100 B/cyc — the sm_103a
// chip-level L2 WRITE-port cap (half the 6300 B/cyc LTS read cap;
// byte-bound, path-independent, chip-shared). The 80 MB write is mandatory
// (d_out poisoned to 0xAA before every timed replay). Floor:
// 80 MB / 3100 B/cyc ≈ 12.6 us kernel + ~2.2 us graph-replay overhead
// ≈ 14.8 us wall. This kernel sits on that floor.
//
// Layout: exact cover, 512 float4 per block, two block-interleaved
// fully-coalesced STG.E.128 per thread — each store instruction's warp
// footprint is one contiguous 128B-aligned 512 B span, giving full-sector
// L2 writes and zero read-modify-write traffic (the only axis measurements
// showed to matter; breaking it cost +75% in R3).

__global__ void __launch_bounds__(256) zero_fill_exact(float4* __restrict__ out, int n4) {
    int base = blockIdx.x * 512 + threadIdx.x;   // block covers [blk*512, blk*512+512)
    const float4 z = make_float4(0.f, 0.f, 0.f, 0.f);
    if (base < n4)        out[base] = z;         // float4 0..255 of the block span
    if (base + 256 < n4)  out[base + 256] = z;   // float4 256..511
}

extern "C" void kernel_launch(void* const* d_in, const int* in_sizes, int n_in,
                              void* d_out, int out_size) {
    (void)d_in; (void)in_sizes; (void)n_in;
    int n4 = out_size / 4;                       // 5,000,000 float4
    int blocks = (n4 + 511) / 512;               // 9766 blocks, exact cover
    zero_fill_exact<<<blocks, 256>>>((float4*)d_out, n4);

    int tail = out_size - n4 * 4;                // 0 for 20M floats; defensive
    if (tail > 0)
        cudaMemsetAsync((float*)d_out + (size_t)n4 * 4, 0, (size_t)tail * sizeof(float), 0);
}